// round 15
// baseline (speedup 1.0000x reference)
#include <cuda_runtime.h>
#include <cuda_fp16.h>
#include <cstdint>
#include <math.h>

// ---------------- Problem constants ----------------
#define N_ROWS 4096
#define D_DIM  2048
#define V_DIM  32000

#define BM 128
#define BN 128
#define BK 64
#define KCHUNKS (D_DIM / BK)   // 32
#define MT (N_ROWS / BM)       // 32
#define NT (V_DIM / BN)        // 250
#define NCTAS (MT * NT)        // 8000

#define ROWB   144             // padded smem row stride (128B data + 16B pad; conflict-free)
#define TILEB  (128 * ROWB)    // 18432 per operand tile
#define STAGEB (2 * TILEB)     // 36864
#define DYNS   (2 * STAGEB)    // 73728 (double buffer)

#define C30LOG2E 43.28085123f  // 30 * log2(e)

// ---------------- Scratch (__device__ globals; no allocs) ----------------
__device__ __align__(16) __half g_A16[(size_t)N_ROWS * D_DIM];  // 16 MB (fp16)
__device__ __align__(16) __half g_B16t[(size_t)V_DIM * D_DIM];  // 131 MB (B^T fp16, k-contiguous)
__device__ float g_sumexp[N_ROWS];   // sum exp(z - 30)
__device__ float g_sumt[N_ROWS];     // sum tanh(d/30)  (sumz = 30 * sumt)
__device__ float g_zt[N_ROWS];       // z at target column
__device__ unsigned int g_done;      // gemm CTA completion counter (reset by conv_a)

// ---------------- asm helpers (baseline ISA only) ----------------
__device__ __forceinline__ uint32_t smem_u32(const void* p) {
    uint32_t a;
    asm("{ .reg .u64 t; cvta.to.shared.u64 t, %1; cvt.u32.u64 %0, t; }" : "=r"(a) : "l"(p));
    return a;
}
__device__ __forceinline__ void cp16(uint32_t dst, const void* src) {
    asm volatile("cp.async.cg.shared.global [%0], [%1], 16;" :: "r"(dst), "l"(src) : "memory");
}
__device__ __forceinline__ void ldm4(uint32_t* r, uint32_t addr) {
    asm volatile("ldmatrix.sync.aligned.m8n8.x4.shared.b16 {%0,%1,%2,%3}, [%4];"
                 : "=r"(r[0]), "=r"(r[1]), "=r"(r[2]), "=r"(r[3]) : "r"(addr));
}
// f16-accumulate MMA: acc packed half2 x2
__device__ __forceinline__ void mma16816_f16(uint32_t* c, const uint32_t* a, const uint32_t* b) {
    asm volatile("mma.sync.aligned.m16n8k16.row.col.f16.f16.f16.f16 "
                 "{%0,%1},{%2,%3,%4,%5},{%6,%7},{%0,%1};"
                 : "+r"(c[0]), "+r"(c[1])
                 : "r"(a[0]), "r"(a[1]), "r"(a[2]), "r"(a[3]), "r"(b[0]), "r"(b[1]));
}
__device__ __forceinline__ float ex2f(float x) {
    float y; asm("ex2.approx.f32 %0, %1;" : "=f"(y) : "f"(x)); return y;
}
__device__ __forceinline__ uint32_t tanh2u(uint32_t x) {
    uint32_t y; asm("tanh.approx.f16x2 %0, %1;" : "=r"(y) : "r"(x)); return y;
}
__device__ __forceinline__ uint32_t hmul2u(uint32_t a, uint32_t b) {
    uint32_t y; asm("mul.f16x2 %0, %1, %2;" : "=r"(y) : "r"(a), "r"(b)); return y;
}
// ---- mbarrier (baseline ISA: no tcgen05/TMA) ----
__device__ __forceinline__ void mbar_init(uint32_t a, uint32_t cnt) {
    asm volatile("mbarrier.init.shared.b64 [%0], %1;" :: "r"(a), "r"(cnt) : "memory");
}
__device__ __forceinline__ void mbar_arrive(uint32_t a) {
    asm volatile("mbarrier.arrive.release.cta.shared::cta.b64 _, [%0];" :: "r"(a) : "memory");
}
__device__ __forceinline__ void cpasync_mbar_arrive(uint32_t a) {
    asm volatile("cp.async.mbarrier.arrive.noinc.shared.b64 [%0];" :: "r"(a) : "memory");
}
__device__ __forceinline__ void mbar_wait(uint32_t a, uint32_t phase) {
    asm volatile(
        "{\n\t.reg .pred P;\n\t"
        "WL_%=:\n\t"
        "mbarrier.try_wait.parity.acquire.cta.shared::cta.b64 P, [%0], %1, 0x989680;\n\t"
        "@!P bra.uni WL_%=;\n\t}"
        :: "r"(a), "r"(phase) : "memory");
}

// ---------------- Prepass A: fp32 -> fp16, row-major (+ accumulator/counter init) ----------------
__global__ __launch_bounds__(256) void conv_a(const float* __restrict__ A) {
    if (blockIdx.x == 0 && threadIdx.x == 0) g_done = 0u;
    if (blockIdx.x < 16) {
        int i = blockIdx.x * 256 + threadIdx.x;
        if (i < N_ROWS) { g_sumexp[i] = 0.0f; g_sumt[i] = 0.0f; g_zt[i] = 0.0f; }
    }
    size_t i = ((size_t)blockIdx.x * 256 + threadIdx.x) * 8;
    float4 f0 = *reinterpret_cast<const float4*>(A + i);
    float4 f1 = *reinterpret_cast<const float4*>(A + i + 4);
    __half2 h0 = __floats2half2_rn(f0.x, f0.y);
    __half2 h1 = __floats2half2_rn(f0.z, f0.w);
    __half2 h2 = __floats2half2_rn(f1.x, f1.y);
    __half2 h3 = __floats2half2_rn(f1.z, f1.w);
    *reinterpret_cast<uint4*>(g_A16 + i) =
        make_uint4(*(uint32_t*)&h0, *(uint32_t*)&h1, *(uint32_t*)&h2, *(uint32_t*)&h3);
}

// ---------------- Prepass B: fp32 [2048,32000] -> fp16 B^T [32000,2048] ----------------
// Coalesced-store version: block = 256 k x 64 n. Phase 1 reads 64 consecutive
// floats per row-group (coalesced), converts to fp16 in smem. Phase 2: each warp
// writes one n-row's 512B segment contiguously (32 lanes x uint4).
__global__ __launch_bounds__(256) void conv_bt(const float* __restrict__ B) {
    __shared__ __half sH[256][68];               // 256 k x 64 n (+4 pad) = 34816 B
    const int nb = blockIdx.x;                   // 500 blocks of 64 n
    const int kb = blockIdx.y;                   // 8 blocks of 256 k
    const int tid = threadIdx.x;
    const int n = tid & 63, k0 = tid >> 6;       // k0 in 0..3
    #pragma unroll 16
    for (int it = 0; it < 64; it++) {
        int k = it * 4 + k0;
        sH[k][n] = __float2half_rn(B[(size_t)(kb * 256 + k) * V_DIM + nb * 64 + n]);
    }
    __syncthreads();
    // 2048 16B output chunks: g = it*256 + tid; n-row = g>>5; chunk-in-row = g&31.
    // A warp covers one n-row (32 consecutive chunks) -> fully coalesced 512B store.
    #pragma unroll
    for (int it = 0; it < 8; it++) {
        int g = it * 256 + tid;
        int nr = g >> 5, ck = g & 31;
        __half tmp[8];
        #pragma unroll
        for (int j = 0; j < 8; j++) tmp[j] = sH[ck * 8 + j][nr];
        *reinterpret_cast<uint4*>(g_B16t + (size_t)(nb * 64 + nr) * D_DIM + kb * 256 + ck * 8) =
            *reinterpret_cast<uint4*>(tmp);
    }
}

// ---------------- Fused GEMM (mma.sync f16 acc, 64x64 warp tiles, BK=64) + CE + final ----------------
// mbarrier producer/consumer pipeline, R13 wait ordering (full-wait first in u=0 —
// the R14 reorder regressed). Last CTA (completion counter) does the scalar reduce.
__global__ __launch_bounds__(128, 3) void gemm_ce(const int* __restrict__ targets,
                                                  float* __restrict__ out) {
    extern __shared__ char smraw[];
    __shared__ __align__(8) uint64_t s_bar[4];   // full0, full1, cons0, cons1
    const uint32_t base = smem_u32(smraw);
    const uint32_t barB = smem_u32(&s_bar[0]);
    const int tid = threadIdx.x, lane = tid & 31, wid = tid >> 5;
    const int wm = wid & 1, wn = wid >> 1;           // warp grid 2 (M) x 2 (N), 64x64 tiles
    const int mt = blockIdx.x, nt = blockIdx.y;      // mt fast -> B tiles L2-resident

    if (tid == 0) {
        mbar_init(barB + 0, 128);    // full[0]
        mbar_init(barB + 8, 128);    // full[1]
        mbar_init(barB + 16, 128);   // consumed[0]
        mbar_init(barB + 24, 128);   // consumed[1]
    }

    // cp.async: per chunk each thread moves 8 A + 8 B 16B pieces.
    const int rA = tid >> 3, cA = tid & 7;           // row 0..15 (+16i), 16B-chunk 0..7
    const char* srcA = (const char*)g_A16 + 2 * ((size_t)(mt * BM + rA) * D_DIM) + cA * 16;
    const char* srcB = (const char*)g_B16t + 2 * ((size_t)(nt * BN + rA) * D_DIM) + cA * 16;
    const uint32_t dA = rA * ROWB + cA * 16;
    const size_t rowStep = 2 * (size_t)16 * D_DIM;   // +16 rows in gmem (bytes)

    // Accumulators: half2-packed, 2 regs per m16n8 frag -> 64 regs total.
    // NEVER dynamically indexed (R5/R6 spill bug).
    uint32_t acc[4][8][2];
    #pragma unroll
    for (int mi = 0; mi < 4; mi++)
        #pragma unroll
        for (int ni = 0; ni < 8; ni++) { acc[mi][ni][0] = 0u; acc[mi][ni][1] = 0u; }

    // ldmatrix lane addressing (same expression form as R9/R11/R12/R13 — do not perturb)
    const uint32_t aOff = (wm * 64 + (lane & 15)) * ROWB + (lane >> 4) * 16;
    const uint32_t bOff = (wn * 64 + ((lane >> 4) << 3) + (lane & 7)) * ROWB + ((lane >> 3) & 1) * 16;

    __syncthreads();   // mbarrier init visible before any use

    // Prologue: prefetch chunk 0 into stage 0, async-arrive full[0]
    {
        #pragma unroll
        for (int i = 0; i < 8; i++) {
            cp16(base + dA + i * 16 * ROWB,         srcA + i * rowStep);
            cp16(base + TILEB + dA + i * 16 * ROWB, srcB + i * rowStep);
        }
        cpasync_mbar_arrive(barB + 0);
    }

    // Main loop: 16 x 2 chunks; stage of chunk (c2+u) is u (compile-time).
    #pragma unroll 1
    for (int c2 = 0; c2 < KCHUNKS; c2 += 2) {
        const uint32_t p = (uint32_t)((c2 >> 1) & 1);   // full parity for both sub-chunks
        // ---- u = 0: chunk c2, stage 0 ----
        {
            mbar_wait(barB + 0, p);                     // full[0]: chunk c2 data ready
            if (c2 > 0) mbar_wait(barB + 24, p ^ 1u);   // consumed[1]: chunk c2-1 done by all
            {   // prefetch chunk c2+1 into stage 1 (always valid: c2 <= 30)
                size_t ko = (size_t)(c2 + 1) * 128;
                #pragma unroll
                for (int i = 0; i < 8; i++) {
                    cp16(base + STAGEB + dA + i * 16 * ROWB,         srcA + ko + i * rowStep);
                    cp16(base + STAGEB + TILEB + dA + i * 16 * ROWB, srcB + ko + i * rowStep);
                }
                cpasync_mbar_arrive(barB + 8);          // full[1]
            }
            const uint32_t Ab = base, Bb = base + TILEB;
            #pragma unroll
            for (int kk = 0; kk < 4; kk++) {
                uint32_t a[4][4], b[8][2];
                #pragma unroll
                for (int pq = 0; pq < 4; pq++) {
                    uint32_t r[4];
                    ldm4(r, Bb + bOff + pq * 16 * ROWB + kk * 32);
                    b[2 * pq][0] = r[0]; b[2 * pq][1] = r[1];
                    b[2 * pq + 1][0] = r[2]; b[2 * pq + 1][1] = r[3];
                }
                #pragma unroll
                for (int mi = 0; mi < 4; mi++)
                    ldm4(a[mi], Ab + aOff + mi * 16 * ROWB + kk * 32);
                #pragma unroll
                for (int mi = 0; mi < 4; mi++)
                    #pragma unroll
                    for (int ni = 0; ni < 8; ni++)
                        mma16816_f16(acc[mi][ni], a[mi], b[ni]);
            }
            mbar_arrive(barB + 16);                     // consumed[0]
        }
        // ---- u = 1: chunk c2+1, stage 1 ----
        {
            mbar_wait(barB + 8, p);                     // full[1]
            const int pf = c2 + 2;
            if (pf < KCHUNKS) {
                mbar_wait(barB + 16, p);                // consumed[0]: chunk c2 done by all
                size_t ko = (size_t)pf * 128;
                #pragma unroll
                for (int i = 0; i < 8; i++) {
                    cp16(base + dA + i * 16 * ROWB,         srcA + ko + i * rowStep);
                    cp16(base + TILEB + dA + i * 16 * ROWB, srcB + ko + i * rowStep);
                }
                cpasync_mbar_arrive(barB + 0);          // full[0]
            }
            const uint32_t Ab = base + STAGEB, Bb = base + STAGEB + TILEB;
            #pragma unroll
            for (int kk = 0; kk < 4; kk++) {
                uint32_t a[4][4], b[8][2];
                #pragma unroll
                for (int pq = 0; pq < 4; pq++) {
                    uint32_t r[4];
                    ldm4(r, Bb + bOff + pq * 16 * ROWB + kk * 32);
                    b[2 * pq][0] = r[0]; b[2 * pq][1] = r[1];
                    b[2 * pq + 1][0] = r[2]; b[2 * pq + 1][1] = r[3];
                }
                #pragma unroll
                for (int mi = 0; mi < 4; mi++)
                    ldm4(a[mi], Ab + aOff + mi * 16 * ROWB + kk * 32);
                #pragma unroll
                for (int mi = 0; mi < 4; mi++)
                    #pragma unroll
                    for (int ni = 0; ni < 8; ni++)
                        mma16816_f16(acc[mi][ni], a[mi], b[ni]);
            }
            mbar_arrive(barB + 24);                     // consumed[1]
        }
    }

    // ---- Fused CE epilogue on half2 accumulators (all indices compile-time) ----
    __half2 i30h = __float2half2_rn(1.0f / 30.0f);
    const uint32_t inv30u = *(uint32_t*)&i30h;
    const int colBase = nt * BN + wn * 64;
    #pragma unroll
    for (int mi = 0; mi < 4; mi++) {
        #pragma unroll
        for (int rh = 0; rh < 2; rh++) {
            const int row = mt * BM + wm * 64 + mi * 16 + rh * 8 + (lane >> 2);
            const int rel = targets[row] - colBase;
            const bool own = (rel >= 0 && rel < 64 && ((rel >> 1) & 3) == (lane & 3));
            float se = 0.0f, st = 0.0f, zsel = 0.0f;
            #pragma unroll
            for (int ni = 0; ni < 8; ni++) {
                uint32_t t2u = tanh2u(hmul2u(acc[mi][ni][rh], inv30u));
                __half2 t2 = *(__half2*)&t2u;
                float t0 = __low2float(t2), t1 = __high2float(t2);
                st += t0 + t1;
                se += ex2f(fmaf(t0, C30LOG2E, -C30LOG2E));   // exp(z-30), z = 30*t
                se += ex2f(fmaf(t1, C30LOG2E, -C30LOG2E));
                if ((rel >> 3) == ni) zsel = (rel & 1) ? t1 : t0;  // ni compile-time -> select
            }
            se += __shfl_xor_sync(0xffffffffu, se, 1);
            se += __shfl_xor_sync(0xffffffffu, se, 2);
            st += __shfl_xor_sync(0xffffffffu, st, 1);
            st += __shfl_xor_sync(0xffffffffu, st, 2);
            if ((lane & 3) == 0) {
                atomicAdd(&g_sumexp[row], se);
                atomicAdd(&g_sumt[row], st);
            }
            if (own) g_zt[row] = 30.0f * zsel;   // unique writer across the grid
        }
    }

    // ---- Last-CTA scalar reduction (replaces the final_reduce launch) ----
    __syncthreads();
    __threadfence();
    __shared__ unsigned int s_rank;
    if (tid == 0) s_rank = atomicAdd(&g_done, 1u);
    __syncthreads();
    if (s_rank == (unsigned)(NCTAS - 1)) {
        float s = 0.0f; int cnt = 0;
        for (int i = tid; i < N_ROWS; i += 128) {
            float lse = 30.0f + logf(g_sumexp[i]);
            bool valid = (targets[i] != -100);
            float nll = lse - g_zt[i];
            float smooth = lse - 30.0f * g_sumt[i] * (1.0f / (float)V_DIM);
            float ce = 0.9f * nll + 0.1f * smooth;
            if (valid) { s += ce + 1e-4f * lse * lse; cnt++; }
        }
        #pragma unroll
        for (int o = 16; o > 0; o >>= 1) {
            s   += __shfl_xor_sync(0xffffffffu, s, o);
            cnt += __shfl_xor_sync(0xffffffffu, cnt, o);
        }
        __shared__ float sf[4];
        __shared__ int   si[4];
        if (lane == 0) { sf[wid] = s; si[wid] = cnt; }
        __syncthreads();
        if (tid == 0)
            out[0] = (sf[0] + sf[1] + sf[2] + sf[3]) /
                     (float)(si[0] + si[1] + si[2] + si[3]);
    }
}

// ---------------- Host launch ----------------
extern "C" void kernel_launch(void* const* d_in, const int* in_sizes, int n_in,
                              void* d_out, int out_size) {
    const float* A       = (const float*)d_in[0];   // [4096, 2048]
    const float* B       = (const float*)d_in[1];   // [2048, 32000]
    const int*   targets = (const int*)d_in[2];     // [4096] int32
    // d_in[3] = bias (0) -> reference skips the bias branch

    cudaFuncSetAttribute(gemm_ce, cudaFuncAttributeMaxDynamicSharedMemorySize, DYNS);

    conv_a<<<(N_ROWS * D_DIM) / (256 * 8), 256>>>(A);
    conv_bt<<<dim3(V_DIM / 64, D_DIM / 256), 256>>>(B);
    gemm_ce<<<dim3(MT, NT), 128, DYNS>>>(targets, (float*)d_out);
}

// round 16
// speedup vs baseline: 1.0559x; 1.0559x over previous
#include <cuda_runtime.h>
#include <cuda_fp16.h>
#include <cstdint>
#include <math.h>

// ---------------- Problem constants ----------------
#define N_ROWS 4096
#define D_DIM  2048
#define V_DIM  32000

#define BM 128
#define BN 128
#define BK 64
#define KCHUNKS (D_DIM / BK)   // 32
#define MT (N_ROWS / BM)       // 32
#define NT (V_DIM / BN)        // 250
#define NCTAS (MT * NT)        // 8000

#define ROWB   144             // padded smem row stride (128B data + 16B pad; conflict-free)
#define TILEB  (128 * ROWB)    // 18432 per operand tile
#define STAGEB (2 * TILEB)     // 36864
#define DYNS   (2 * STAGEB)    // 73728 (double buffer)

#define C30LOG2E 43.28085123f  // 30 * log2(e)

// ---------------- Scratch (__device__ globals; no allocs) ----------------
__device__ __align__(16) __half g_A16[(size_t)N_ROWS * D_DIM];  // 16 MB (fp16)
__device__ __align__(16) __half g_B16t[(size_t)V_DIM * D_DIM];  // 131 MB (B^T fp16, k-contiguous)
__device__ float g_sumexp[N_ROWS];   // sum exp(z - 30)
__device__ float g_sumt[N_ROWS];     // sum tanh(d/30)  (sumz = 30 * sumt)
__device__ float g_zt[N_ROWS];       // z at target column
__device__ unsigned int g_done;      // gemm CTA completion counter (reset by conv_a)

// ---------------- asm helpers (baseline ISA only) ----------------
__device__ __forceinline__ uint32_t smem_u32(const void* p) {
    uint32_t a;
    asm("{ .reg .u64 t; cvta.to.shared.u64 t, %1; cvt.u32.u64 %0, t; }" : "=r"(a) : "l"(p));
    return a;
}
__device__ __forceinline__ void cp16(uint32_t dst, const void* src) {
    asm volatile("cp.async.cg.shared.global [%0], [%1], 16;" :: "r"(dst), "l"(src) : "memory");
}
__device__ __forceinline__ void ldm4(uint32_t* r, uint32_t addr) {
    asm volatile("ldmatrix.sync.aligned.m8n8.x4.shared.b16 {%0,%1,%2,%3}, [%4];"
                 : "=r"(r[0]), "=r"(r[1]), "=r"(r[2]), "=r"(r[3]) : "r"(addr));
}
// f16-accumulate MMA: acc packed half2 x2
__device__ __forceinline__ void mma16816_f16(uint32_t* c, const uint32_t* a, const uint32_t* b) {
    asm volatile("mma.sync.aligned.m16n8k16.row.col.f16.f16.f16.f16 "
                 "{%0,%1},{%2,%3,%4,%5},{%6,%7},{%0,%1};"
                 : "+r"(c[0]), "+r"(c[1])
                 : "r"(a[0]), "r"(a[1]), "r"(a[2]), "r"(a[3]), "r"(b[0]), "r"(b[1]));
}
__device__ __forceinline__ float ex2f(float x) {
    float y; asm("ex2.approx.f32 %0, %1;" : "=f"(y) : "f"(x)); return y;
}
__device__ __forceinline__ uint32_t tanh2u(uint32_t x) {
    uint32_t y; asm("tanh.approx.f16x2 %0, %1;" : "=r"(y) : "r"(x)); return y;
}
__device__ __forceinline__ uint32_t hmul2u(uint32_t a, uint32_t b) {
    uint32_t y; asm("mul.f16x2 %0, %1, %2;" : "=r"(y) : "r"(a), "r"(b)); return y;
}
// ---- mbarrier (baseline ISA: no tcgen05/TMA) ----
__device__ __forceinline__ void mbar_init(uint32_t a, uint32_t cnt) {
    asm volatile("mbarrier.init.shared.b64 [%0], %1;" :: "r"(a), "r"(cnt) : "memory");
}
__device__ __forceinline__ void mbar_arrive(uint32_t a) {
    asm volatile("mbarrier.arrive.release.cta.shared::cta.b64 _, [%0];" :: "r"(a) : "memory");
}
__device__ __forceinline__ void cpasync_mbar_arrive(uint32_t a) {
    asm volatile("cp.async.mbarrier.arrive.noinc.shared.b64 [%0];" :: "r"(a) : "memory");
}
__device__ __forceinline__ void mbar_wait(uint32_t a, uint32_t phase) {
    asm volatile(
        "{\n\t.reg .pred P;\n\t"
        "WL_%=:\n\t"
        "mbarrier.try_wait.parity.acquire.cta.shared::cta.b64 P, [%0], %1, 0x989680;\n\t"
        "@!P bra.uni WL_%=;\n\t}"
        :: "r"(a), "r"(phase) : "memory");
}

// ---------------- Prepass A: fp32 -> fp16, row-major (+ accumulator/counter init) ----------------
__global__ __launch_bounds__(256) void conv_a(const float* __restrict__ A) {
    if (blockIdx.x == 0 && threadIdx.x == 0) g_done = 0u;
    if (blockIdx.x < 16) {
        int i = blockIdx.x * 256 + threadIdx.x;
        if (i < N_ROWS) { g_sumexp[i] = 0.0f; g_sumt[i] = 0.0f; g_zt[i] = 0.0f; }
    }
    size_t i = ((size_t)blockIdx.x * 256 + threadIdx.x) * 8;
    float4 f0 = *reinterpret_cast<const float4*>(A + i);
    float4 f1 = *reinterpret_cast<const float4*>(A + i + 4);
    __half2 h0 = __floats2half2_rn(f0.x, f0.y);
    __half2 h1 = __floats2half2_rn(f0.z, f0.w);
    __half2 h2 = __floats2half2_rn(f1.x, f1.y);
    __half2 h3 = __floats2half2_rn(f1.z, f1.w);
    *reinterpret_cast<uint4*>(g_A16 + i) =
        make_uint4(*(uint32_t*)&h0, *(uint32_t*)&h1, *(uint32_t*)&h2, *(uint32_t*)&h3);
}

// ---------------- Prepass B: fp32 [2048,32000] -> fp16 B^T [32000,2048] ----------------
// R13/R14 version (profiled-good): wide coalesced reads (1024B/row), conflict-free
// float smem transpose, 64B-contiguous stores. The R15 "coalesced" rewrite had
// 8-way smem bank conflicts and narrow reads — reverted.
__global__ __launch_bounds__(256) void conv_bt(const float* __restrict__ B) {
    __shared__ float sT[32][257];
    const int nb = blockIdx.x;   // 125 blocks of 256 n
    const int kb = blockIdx.y;   // 64 blocks of 32 k
    const int tid = threadIdx.x;
    #pragma unroll
    for (int k = 0; k < 32; k++)
        sT[k][tid] = B[(size_t)(kb * 32 + k) * V_DIM + nb * 256 + tid];
    __syncthreads();
    __half* dst = g_B16t + (size_t)(nb * 256 + tid) * D_DIM + kb * 32;
    uint32_t pk[16];
    #pragma unroll
    for (int j = 0; j < 16; j++) {
        __half2 p = __floats2half2_rn(sT[2 * j][tid], sT[2 * j + 1][tid]);
        pk[j] = *(uint32_t*)&p;
    }
    #pragma unroll
    for (int q = 0; q < 4; q++)
        *reinterpret_cast<uint4*>(dst + q * 8) =
            make_uint4(pk[4 * q], pk[4 * q + 1], pk[4 * q + 2], pk[4 * q + 3]);
}

// ---------------- Fused GEMM (mma.sync f16 acc, 64x64 warp tiles, BK=64) + CE + final ----------------
// mbarrier producer/consumer pipeline, R13 wait ordering (full-wait first in u=0).
// Last CTA (completion counter) performs the scalar reduction — no separate kernel.
__global__ __launch_bounds__(128, 3) void gemm_ce(const int* __restrict__ targets,
                                                  float* __restrict__ out) {
    extern __shared__ char smraw[];
    __shared__ __align__(8) uint64_t s_bar[4];   // full0, full1, cons0, cons1
    const uint32_t base = smem_u32(smraw);
    const uint32_t barB = smem_u32(&s_bar[0]);
    const int tid = threadIdx.x, lane = tid & 31, wid = tid >> 5;
    const int wm = wid & 1, wn = wid >> 1;           // warp grid 2 (M) x 2 (N), 64x64 tiles
    const int mt = blockIdx.x, nt = blockIdx.y;      // mt fast -> B tiles L2-resident

    if (tid == 0) {
        mbar_init(barB + 0, 128);    // full[0]
        mbar_init(barB + 8, 128);    // full[1]
        mbar_init(barB + 16, 128);   // consumed[0]
        mbar_init(barB + 24, 128);   // consumed[1]
    }

    // cp.async: per chunk each thread moves 8 A + 8 B 16B pieces.
    const int rA = tid >> 3, cA = tid & 7;           // row 0..15 (+16i), 16B-chunk 0..7
    const char* srcA = (const char*)g_A16 + 2 * ((size_t)(mt * BM + rA) * D_DIM) + cA * 16;
    const char* srcB = (const char*)g_B16t + 2 * ((size_t)(nt * BN + rA) * D_DIM) + cA * 16;
    const uint32_t dA = rA * ROWB + cA * 16;
    const size_t rowStep = 2 * (size_t)16 * D_DIM;   // +16 rows in gmem (bytes)

    // Accumulators: half2-packed, 2 regs per m16n8 frag -> 64 regs total.
    // NEVER dynamically indexed (R5/R6 spill bug).
    uint32_t acc[4][8][2];
    #pragma unroll
    for (int mi = 0; mi < 4; mi++)
        #pragma unroll
        for (int ni = 0; ni < 8; ni++) { acc[mi][ni][0] = 0u; acc[mi][ni][1] = 0u; }

    // ldmatrix lane addressing (same expression form as R9/R11/R12/R13 — do not perturb)
    const uint32_t aOff = (wm * 64 + (lane & 15)) * ROWB + (lane >> 4) * 16;
    const uint32_t bOff = (wn * 64 + ((lane >> 4) << 3) + (lane & 7)) * ROWB + ((lane >> 3) & 1) * 16;

    __syncthreads();   // mbarrier init visible before any use

    // Prologue: prefetch chunk 0 into stage 0, async-arrive full[0]
    {
        #pragma unroll
        for (int i = 0; i < 8; i++) {
            cp16(base + dA + i * 16 * ROWB,         srcA + i * rowStep);
            cp16(base + TILEB + dA + i * 16 * ROWB, srcB + i * rowStep);
        }
        cpasync_mbar_arrive(barB + 0);
    }

    // Main loop: 16 x 2 chunks; stage of chunk (c2+u) is u (compile-time).
    #pragma unroll 1
    for (int c2 = 0; c2 < KCHUNKS; c2 += 2) {
        const uint32_t p = (uint32_t)((c2 >> 1) & 1);   // full parity for both sub-chunks
        // ---- u = 0: chunk c2, stage 0 ----
        {
            mbar_wait(barB + 0, p);                     // full[0]: chunk c2 data ready
            if (c2 > 0) mbar_wait(barB + 24, p ^ 1u);   // consumed[1]: chunk c2-1 done by all
            {   // prefetch chunk c2+1 into stage 1 (always valid: c2 <= 30)
                size_t ko = (size_t)(c2 + 1) * 128;
                #pragma unroll
                for (int i = 0; i < 8; i++) {
                    cp16(base + STAGEB + dA + i * 16 * ROWB,         srcA + ko + i * rowStep);
                    cp16(base + STAGEB + TILEB + dA + i * 16 * ROWB, srcB + ko + i * rowStep);
                }
                cpasync_mbar_arrive(barB + 8);          // full[1]
            }
            const uint32_t Ab = base, Bb = base + TILEB;
            #pragma unroll
            for (int kk = 0; kk < 4; kk++) {
                uint32_t a[4][4], b[8][2];
                #pragma unroll
                for (int pq = 0; pq < 4; pq++) {
                    uint32_t r[4];
                    ldm4(r, Bb + bOff + pq * 16 * ROWB + kk * 32);
                    b[2 * pq][0] = r[0]; b[2 * pq][1] = r[1];
                    b[2 * pq + 1][0] = r[2]; b[2 * pq + 1][1] = r[3];
                }
                #pragma unroll
                for (int mi = 0; mi < 4; mi++)
                    ldm4(a[mi], Ab + aOff + mi * 16 * ROWB + kk * 32);
                #pragma unroll
                for (int mi = 0; mi < 4; mi++)
                    #pragma unroll
                    for (int ni = 0; ni < 8; ni++)
                        mma16816_f16(acc[mi][ni], a[mi], b[ni]);
            }
            mbar_arrive(barB + 16);                     // consumed[0]
        }
        // ---- u = 1: chunk c2+1, stage 1 ----
        {
            mbar_wait(barB + 8, p);                     // full[1]
            const int pf = c2 + 2;
            if (pf < KCHUNKS) {
                mbar_wait(barB + 16, p);                // consumed[0]: chunk c2 done by all
                size_t ko = (size_t)pf * 128;
                #pragma unroll
                for (int i = 0; i < 8; i++) {
                    cp16(base + dA + i * 16 * ROWB,         srcA + ko + i * rowStep);
                    cp16(base + TILEB + dA + i * 16 * ROWB, srcB + ko + i * rowStep);
                }
                cpasync_mbar_arrive(barB + 0);          // full[0]
            }
            const uint32_t Ab = base + STAGEB, Bb = base + STAGEB + TILEB;
            #pragma unroll
            for (int kk = 0; kk < 4; kk++) {
                uint32_t a[4][4], b[8][2];
                #pragma unroll
                for (int pq = 0; pq < 4; pq++) {
                    uint32_t r[4];
                    ldm4(r, Bb + bOff + pq * 16 * ROWB + kk * 32);
                    b[2 * pq][0] = r[0]; b[2 * pq][1] = r[1];
                    b[2 * pq + 1][0] = r[2]; b[2 * pq + 1][1] = r[3];
                }
                #pragma unroll
                for (int mi = 0; mi < 4; mi++)
                    ldm4(a[mi], Ab + aOff + mi * 16 * ROWB + kk * 32);
                #pragma unroll
                for (int mi = 0; mi < 4; mi++)
                    #pragma unroll
                    for (int ni = 0; ni < 8; ni++)
                        mma16816_f16(acc[mi][ni], a[mi], b[ni]);
            }
            mbar_arrive(barB + 24);                     // consumed[1]
        }
    }

    // ---- Fused CE epilogue on half2 accumulators (all indices compile-time) ----
    __half2 i30h = __float2half2_rn(1.0f / 30.0f);
    const uint32_t inv30u = *(uint32_t*)&i30h;
    const int colBase = nt * BN + wn * 64;
    #pragma unroll
    for (int mi = 0; mi < 4; mi++) {
        #pragma unroll
        for (int rh = 0; rh < 2; rh++) {
            const int row = mt * BM + wm * 64 + mi * 16 + rh * 8 + (lane >> 2);
            const int rel = targets[row] - colBase;
            const bool own = (rel >= 0 && rel < 64 && ((rel >> 1) & 3) == (lane & 3));
            float se = 0.0f, st = 0.0f, zsel = 0.0f;
            #pragma unroll
            for (int ni = 0; ni < 8; ni++) {
                uint32_t t2u = tanh2u(hmul2u(acc[mi][ni][rh], inv30u));
                __half2 t2 = *(__half2*)&t2u;
                float t0 = __low2float(t2), t1 = __high2float(t2);
                st += t0 + t1;
                se += ex2f(fmaf(t0, C30LOG2E, -C30LOG2E));   // exp(z-30), z = 30*t
                se += ex2f(fmaf(t1, C30LOG2E, -C30LOG2E));
                if ((rel >> 3) == ni) zsel = (rel & 1) ? t1 : t0;  // ni compile-time -> select
            }
            se += __shfl_xor_sync(0xffffffffu, se, 1);
            se += __shfl_xor_sync(0xffffffffu, se, 2);
            st += __shfl_xor_sync(0xffffffffu, st, 1);
            st += __shfl_xor_sync(0xffffffffu, st, 2);
            if ((lane & 3) == 0) {
                atomicAdd(&g_sumexp[row], se);
                atomicAdd(&g_sumt[row], st);
            }
            if (own) g_zt[row] = 30.0f * zsel;   // unique writer across the grid
        }
    }

    // ---- Last-CTA scalar reduction (replaces the final_reduce launch) ----
    __syncthreads();
    __threadfence();
    __shared__ unsigned int s_rank;
    if (tid == 0) s_rank = atomicAdd(&g_done, 1u);
    __syncthreads();
    if (s_rank == (unsigned)(NCTAS - 1)) {
        float s = 0.0f; int cnt = 0;
        for (int i = tid; i < N_ROWS; i += 128) {
            float lse = 30.0f + logf(g_sumexp[i]);
            bool valid = (targets[i] != -100);
            float nll = lse - g_zt[i];
            float smooth = lse - 30.0f * g_sumt[i] * (1.0f / (float)V_DIM);
            float ce = 0.9f * nll + 0.1f * smooth;
            if (valid) { s += ce + 1e-4f * lse * lse; cnt++; }
        }
        #pragma unroll
        for (int o = 16; o > 0; o >>= 1) {
            s   += __shfl_xor_sync(0xffffffffu, s, o);
            cnt += __shfl_xor_sync(0xffffffffu, cnt, o);
        }
        __shared__ float sf[4];
        __shared__ int   si[4];
        if (lane == 0) { sf[wid] = s; si[wid] = cnt; }
        __syncthreads();
        if (tid == 0)
            out[0] = (sf[0] + sf[1] + sf[2] + sf[3]) /
                     (float)(si[0] + si[1] + si[2] + si[3]);
    }
}

// ---------------- Host launch ----------------
extern "C" void kernel_launch(void* const* d_in, const int* in_sizes, int n_in,
                              void* d_out, int out_size) {
    const float* A       = (const float*)d_in[0];   // [4096, 2048]
    const float* B       = (const float*)d_in[1];   // [2048, 32000]
    const int*   targets = (const int*)d_in[2];     // [4096] int32
    // d_in[3] = bias (0) -> reference skips the bias branch

    cudaFuncSetAttribute(gemm_ce, cudaFuncAttributeMaxDynamicSharedMemorySize, DYNS);

    conv_a<<<(N_ROWS * D_DIM) / (256 * 8), 256>>>(A);
    conv_bt<<<dim3(V_DIM / 256, D_DIM / 32), 256>>>(B);
    gemm_ce<<<dim3(MT, NT), 128, DYNS>>>(targets, (float*)d_out);
}

// round 17
// speedup vs baseline: 1.0574x; 1.0014x over previous
#include <cuda_runtime.h>
#include <cuda_fp16.h>
#include <cstdint>
#include <math.h>

// ---------------- Problem constants ----------------
#define N_ROWS 4096
#define D_DIM  2048
#define V_DIM  32000

#define BM 128
#define BN 128
#define BK 64
#define KCHUNKS (D_DIM / BK)   // 32
#define MT (N_ROWS / BM)       // 32
#define NT (V_DIM / BN)        // 250
#define NCTAS (MT * NT)        // 8000

#define ROWB   144             // padded smem row stride (128B data + 16B pad; conflict-free)
#define TILEB  (128 * ROWB)    // 18432 per operand tile
#define STAGEB (2 * TILEB)     // 36864
#define DYNS   (2 * STAGEB)    // 73728 (double buffer)

#define C30LOG2E 43.28085123f  // 30 * log2(e)

// ---------------- Scratch (__device__ globals; no allocs) ----------------
__device__ __align__(16) __half g_A16[(size_t)N_ROWS * D_DIM];  // 16 MB (fp16)
__device__ __align__(16) __half g_B16t[(size_t)V_DIM * D_DIM];  // 131 MB (B^T fp16, k-contiguous)
__device__ float g_sumexp[N_ROWS];   // sum exp(z - 30)
__device__ float g_sumt[N_ROWS];     // sum tanh(d/30)  (sumz = 30 * sumt)
__device__ float g_zt[N_ROWS];       // z at target column
__device__ unsigned int g_done;      // gemm CTA completion counter (reset by prep)

// ---------------- asm helpers (baseline ISA only) ----------------
__device__ __forceinline__ uint32_t smem_u32(const void* p) {
    uint32_t a;
    asm("{ .reg .u64 t; cvta.to.shared.u64 t, %1; cvt.u32.u64 %0, t; }" : "=r"(a) : "l"(p));
    return a;
}
__device__ __forceinline__ void cp16(uint32_t dst, const void* src) {
    asm volatile("cp.async.cg.shared.global [%0], [%1], 16;" :: "r"(dst), "l"(src) : "memory");
}
__device__ __forceinline__ void ldm4(uint32_t* r, uint32_t addr) {
    asm volatile("ldmatrix.sync.aligned.m8n8.x4.shared.b16 {%0,%1,%2,%3}, [%4];"
                 : "=r"(r[0]), "=r"(r[1]), "=r"(r[2]), "=r"(r[3]) : "r"(addr));
}
// f16-accumulate MMA: acc packed half2 x2
__device__ __forceinline__ void mma16816_f16(uint32_t* c, const uint32_t* a, const uint32_t* b) {
    asm volatile("mma.sync.aligned.m16n8k16.row.col.f16.f16.f16.f16 "
                 "{%0,%1},{%2,%3,%4,%5},{%6,%7},{%0,%1};"
                 : "+r"(c[0]), "+r"(c[1])
                 : "r"(a[0]), "r"(a[1]), "r"(a[2]), "r"(a[3]), "r"(b[0]), "r"(b[1]));
}
__device__ __forceinline__ float ex2f(float x) {
    float y; asm("ex2.approx.f32 %0, %1;" : "=f"(y) : "f"(x)); return y;
}
__device__ __forceinline__ uint32_t tanh2u(uint32_t x) {
    uint32_t y; asm("tanh.approx.f16x2 %0, %1;" : "=r"(y) : "r"(x)); return y;
}
__device__ __forceinline__ uint32_t hmul2u(uint32_t a, uint32_t b) {
    uint32_t y; asm("mul.f16x2 %0, %1, %2;" : "=r"(y) : "r"(a), "r"(b)); return y;
}
// ---- mbarrier (baseline ISA: no tcgen05/TMA) ----
__device__ __forceinline__ void mbar_init(uint32_t a, uint32_t cnt) {
    asm volatile("mbarrier.init.shared.b64 [%0], %1;" :: "r"(a), "r"(cnt) : "memory");
}
__device__ __forceinline__ void mbar_arrive(uint32_t a) {
    asm volatile("mbarrier.arrive.release.cta.shared::cta.b64 _, [%0];" :: "r"(a) : "memory");
}
__device__ __forceinline__ void cpasync_mbar_arrive(uint32_t a) {
    asm volatile("cp.async.mbarrier.arrive.noinc.shared.b64 [%0];" :: "r"(a) : "memory");
}
__device__ __forceinline__ void mbar_wait(uint32_t a, uint32_t phase) {
    asm volatile(
        "{\n\t.reg .pred P;\n\t"
        "WL_%=:\n\t"
        "mbarrier.try_wait.parity.acquire.cta.shared::cta.b64 P, [%0], %1, 0x989680;\n\t"
        "@!P bra.uni WL_%=;\n\t}"
        :: "r"(a), "r"(phase) : "memory");
}

// ---------------- Unified prep: B^T transpose+convert, A convert, init ----------------
// Grid 125 x 64, 256 thr (= R16 conv_bt shape, profiled-good). Each block also
// absorbs a slice of the A fp32->fp16 conversion (8 elems per low-gid thread)
// and the accumulator/counter init — deletes the separate conv_a launch.
__global__ __launch_bounds__(256) void prep(const float* __restrict__ B,
                                            const float* __restrict__ A) {
    const int nb = blockIdx.x;   // 125 blocks of 256 n
    const int kb = blockIdx.y;   // 64 blocks of 32 k
    const int tid = threadIdx.x;
    const int bid = kb * 125 + nb;               // linear block id, 0..7999
    const size_t gid = (size_t)bid * 256 + tid;  // linear thread id

    // ---- absorbed conv_a: 1,048,576 uint4 stores cover A (8.4M fp32) ----
    if (gid < (size_t)(N_ROWS * D_DIM / 8)) {
        size_t i = gid * 8;
        float4 f0 = *reinterpret_cast<const float4*>(A + i);
        float4 f1 = *reinterpret_cast<const float4*>(A + i + 4);
        __half2 h0 = __floats2half2_rn(f0.x, f0.y);
        __half2 h1 = __floats2half2_rn(f0.z, f0.w);
        __half2 h2 = __floats2half2_rn(f1.x, f1.y);
        __half2 h3 = __floats2half2_rn(f1.z, f1.w);
        *reinterpret_cast<uint4*>(g_A16 + i) =
            make_uint4(*(uint32_t*)&h0, *(uint32_t*)&h1, *(uint32_t*)&h2, *(uint32_t*)&h3);
    }
    // ---- absorbed init ----
    if (gid < N_ROWS) { g_sumexp[gid] = 0.0f; g_sumt[gid] = 0.0f; g_zt[gid] = 0.0f; }
    if (gid == 0) g_done = 0u;

    // ---- conv_bt (R16 form: wide coalesced reads, conflict-free transpose) ----
    __shared__ float sT[32][257];
    #pragma unroll
    for (int k = 0; k < 32; k++)
        sT[k][tid] = B[(size_t)(kb * 32 + k) * V_DIM + nb * 256 + tid];
    __syncthreads();
    __half* dst = g_B16t + (size_t)(nb * 256 + tid) * D_DIM + kb * 32;
    uint32_t pk[16];
    #pragma unroll
    for (int j = 0; j < 16; j++) {
        __half2 p = __floats2half2_rn(sT[2 * j][tid], sT[2 * j + 1][tid]);
        pk[j] = *(uint32_t*)&p;
    }
    #pragma unroll
    for (int q = 0; q < 4; q++)
        *reinterpret_cast<uint4*>(dst + q * 8) =
            make_uint4(pk[4 * q], pk[4 * q + 1], pk[4 * q + 2], pk[4 * q + 3]);
}

// ---------------- Fused GEMM (mma.sync f16 acc, 64x64 warp tiles, BK=64) + CE + final ----------------
// Byte-identical to R16: mbarrier producer/consumer pipeline, R13 wait ordering,
// last-CTA scalar reduction.
__global__ __launch_bounds__(128, 3) void gemm_ce(const int* __restrict__ targets,
                                                  float* __restrict__ out) {
    extern __shared__ char smraw[];
    __shared__ __align__(8) uint64_t s_bar[4];   // full0, full1, cons0, cons1
    const uint32_t base = smem_u32(smraw);
    const uint32_t barB = smem_u32(&s_bar[0]);
    const int tid = threadIdx.x, lane = tid & 31, wid = tid >> 5;
    const int wm = wid & 1, wn = wid >> 1;           // warp grid 2 (M) x 2 (N), 64x64 tiles
    const int mt = blockIdx.x, nt = blockIdx.y;      // mt fast -> B tiles L2-resident

    if (tid == 0) {
        mbar_init(barB + 0, 128);    // full[0]
        mbar_init(barB + 8, 128);    // full[1]
        mbar_init(barB + 16, 128);   // consumed[0]
        mbar_init(barB + 24, 128);   // consumed[1]
    }

    // cp.async: per chunk each thread moves 8 A + 8 B 16B pieces.
    const int rA = tid >> 3, cA = tid & 7;           // row 0..15 (+16i), 16B-chunk 0..7
    const char* srcA = (const char*)g_A16 + 2 * ((size_t)(mt * BM + rA) * D_DIM) + cA * 16;
    const char* srcB = (const char*)g_B16t + 2 * ((size_t)(nt * BN + rA) * D_DIM) + cA * 16;
    const uint32_t dA = rA * ROWB + cA * 16;
    const size_t rowStep = 2 * (size_t)16 * D_DIM;   // +16 rows in gmem (bytes)

    // Accumulators: half2-packed, 2 regs per m16n8 frag -> 64 regs total.
    // NEVER dynamically indexed (R5/R6 spill bug).
    uint32_t acc[4][8][2];
    #pragma unroll
    for (int mi = 0; mi < 4; mi++)
        #pragma unroll
        for (int ni = 0; ni < 8; ni++) { acc[mi][ni][0] = 0u; acc[mi][ni][1] = 0u; }

    // ldmatrix lane addressing (same expression form as R9/R11/R12/R13 — do not perturb)
    const uint32_t aOff = (wm * 64 + (lane & 15)) * ROWB + (lane >> 4) * 16;
    const uint32_t bOff = (wn * 64 + ((lane >> 4) << 3) + (lane & 7)) * ROWB + ((lane >> 3) & 1) * 16;

    __syncthreads();   // mbarrier init visible before any use

    // Prologue: prefetch chunk 0 into stage 0, async-arrive full[0]
    {
        #pragma unroll
        for (int i = 0; i < 8; i++) {
            cp16(base + dA + i * 16 * ROWB,         srcA + i * rowStep);
            cp16(base + TILEB + dA + i * 16 * ROWB, srcB + i * rowStep);
        }
        cpasync_mbar_arrive(barB + 0);
    }

    // Main loop: 16 x 2 chunks; stage of chunk (c2+u) is u (compile-time).
    #pragma unroll 1
    for (int c2 = 0; c2 < KCHUNKS; c2 += 2) {
        const uint32_t p = (uint32_t)((c2 >> 1) & 1);   // full parity for both sub-chunks
        // ---- u = 0: chunk c2, stage 0 ----
        {
            mbar_wait(barB + 0, p);                     // full[0]: chunk c2 data ready
            if (c2 > 0) mbar_wait(barB + 24, p ^ 1u);   // consumed[1]: chunk c2-1 done by all
            {   // prefetch chunk c2+1 into stage 1 (always valid: c2 <= 30)
                size_t ko = (size_t)(c2 + 1) * 128;
                #pragma unroll
                for (int i = 0; i < 8; i++) {
                    cp16(base + STAGEB + dA + i * 16 * ROWB,         srcA + ko + i * rowStep);
                    cp16(base + STAGEB + TILEB + dA + i * 16 * ROWB, srcB + ko + i * rowStep);
                }
                cpasync_mbar_arrive(barB + 8);          // full[1]
            }
            const uint32_t Ab = base, Bb = base + TILEB;
            #pragma unroll
            for (int kk = 0; kk < 4; kk++) {
                uint32_t a[4][4], b[8][2];
                #pragma unroll
                for (int pq = 0; pq < 4; pq++) {
                    uint32_t r[4];
                    ldm4(r, Bb + bOff + pq * 16 * ROWB + kk * 32);
                    b[2 * pq][0] = r[0]; b[2 * pq][1] = r[1];
                    b[2 * pq + 1][0] = r[2]; b[2 * pq + 1][1] = r[3];
                }
                #pragma unroll
                for (int mi = 0; mi < 4; mi++)
                    ldm4(a[mi], Ab + aOff + mi * 16 * ROWB + kk * 32);
                #pragma unroll
                for (int mi = 0; mi < 4; mi++)
                    #pragma unroll
                    for (int ni = 0; ni < 8; ni++)
                        mma16816_f16(acc[mi][ni], a[mi], b[ni]);
            }
            mbar_arrive(barB + 16);                     // consumed[0]
        }
        // ---- u = 1: chunk c2+1, stage 1 ----
        {
            mbar_wait(barB + 8, p);                     // full[1]
            const int pf = c2 + 2;
            if (pf < KCHUNKS) {
                mbar_wait(barB + 16, p);                // consumed[0]: chunk c2 done by all
                size_t ko = (size_t)pf * 128;
                #pragma unroll
                for (int i = 0; i < 8; i++) {
                    cp16(base + dA + i * 16 * ROWB,         srcA + ko + i * rowStep);
                    cp16(base + TILEB + dA + i * 16 * ROWB, srcB + ko + i * rowStep);
                }
                cpasync_mbar_arrive(barB + 0);          // full[0]
            }
            const uint32_t Ab = base + STAGEB, Bb = base + STAGEB + TILEB;
            #pragma unroll
            for (int kk = 0; kk < 4; kk++) {
                uint32_t a[4][4], b[8][2];
                #pragma unroll
                for (int pq = 0; pq < 4; pq++) {
                    uint32_t r[4];
                    ldm4(r, Bb + bOff + pq * 16 * ROWB + kk * 32);
                    b[2 * pq][0] = r[0]; b[2 * pq][1] = r[1];
                    b[2 * pq + 1][0] = r[2]; b[2 * pq + 1][1] = r[3];
                }
                #pragma unroll
                for (int mi = 0; mi < 4; mi++)
                    ldm4(a[mi], Ab + aOff + mi * 16 * ROWB + kk * 32);
                #pragma unroll
                for (int mi = 0; mi < 4; mi++)
                    #pragma unroll
                    for (int ni = 0; ni < 8; ni++)
                        mma16816_f16(acc[mi][ni], a[mi], b[ni]);
            }
            mbar_arrive(barB + 24);                     // consumed[1]
        }
    }

    // ---- Fused CE epilogue on half2 accumulators (all indices compile-time) ----
    __half2 i30h = __float2half2_rn(1.0f / 30.0f);
    const uint32_t inv30u = *(uint32_t*)&i30h;
    const int colBase = nt * BN + wn * 64;
    #pragma unroll
    for (int mi = 0; mi < 4; mi++) {
        #pragma unroll
        for (int rh = 0; rh < 2; rh++) {
            const int row = mt * BM + wm * 64 + mi * 16 + rh * 8 + (lane >> 2);
            const int rel = targets[row] - colBase;
            const bool own = (rel >= 0 && rel < 64 && ((rel >> 1) & 3) == (lane & 3));
            float se = 0.0f, st = 0.0f, zsel = 0.0f;
            #pragma unroll
            for (int ni = 0; ni < 8; ni++) {
                uint32_t t2u = tanh2u(hmul2u(acc[mi][ni][rh], inv30u));
                __half2 t2 = *(__half2*)&t2u;
                float t0 = __low2float(t2), t1 = __high2float(t2);
                st += t0 + t1;
                se += ex2f(fmaf(t0, C30LOG2E, -C30LOG2E));   // exp(z-30), z = 30*t
                se += ex2f(fmaf(t1, C30LOG2E, -C30LOG2E));
                if ((rel >> 3) == ni) zsel = (rel & 1) ? t1 : t0;  // ni compile-time -> select
            }
            se += __shfl_xor_sync(0xffffffffu, se, 1);
            se += __shfl_xor_sync(0xffffffffu, se, 2);
            st += __shfl_xor_sync(0xffffffffu, st, 1);
            st += __shfl_xor_sync(0xffffffffu, st, 2);
            if ((lane & 3) == 0) {
                atomicAdd(&g_sumexp[row], se);
                atomicAdd(&g_sumt[row], st);
            }
            if (own) g_zt[row] = 30.0f * zsel;   // unique writer across the grid
        }
    }

    // ---- Last-CTA scalar reduction (no separate final kernel) ----
    __syncthreads();
    __threadfence();
    __shared__ unsigned int s_rank;
    if (tid == 0) s_rank = atomicAdd(&g_done, 1u);
    __syncthreads();
    if (s_rank == (unsigned)(NCTAS - 1)) {
        float s = 0.0f; int cnt = 0;
        for (int i = tid; i < N_ROWS; i += 128) {
            float lse = 30.0f + logf(g_sumexp[i]);
            bool valid = (targets[i] != -100);
            float nll = lse - g_zt[i];
            float smooth = lse - 30.0f * g_sumt[i] * (1.0f / (float)V_DIM);
            float ce = 0.9f * nll + 0.1f * smooth;
            if (valid) { s += ce + 1e-4f * lse * lse; cnt++; }
        }
        #pragma unroll
        for (int o = 16; o > 0; o >>= 1) {
            s   += __shfl_xor_sync(0xffffffffu, s, o);
            cnt += __shfl_xor_sync(0xffffffffu, cnt, o);
        }
        __shared__ float sf[4];
        __shared__ int   si[4];
        if (lane == 0) { sf[wid] = s; si[wid] = cnt; }
        __syncthreads();
        if (tid == 0)
            out[0] = (sf[0] + sf[1] + sf[2] + sf[3]) /
                     (float)(si[0] + si[1] + si[2] + si[3]);
    }
}

// ---------------- Host launch ----------------
extern "C" void kernel_launch(void* const* d_in, const int* in_sizes, int n_in,
                              void* d_out, int out_size) {
    const float* A       = (const float*)d_in[0];   // [4096, 2048]
    const float* B       = (const float*)d_in[1];   // [2048, 32000]
    const int*   targets = (const int*)d_in[2];     // [4096] int32
    // d_in[3] = bias (0) -> reference skips the bias branch

    cudaFuncSetAttribute(gemm_ce, cudaFuncAttributeMaxDynamicSharedMemorySize, DYNS);

    prep<<<dim3(V_DIM / 256, D_DIM / 32), 256>>>(B, A);
    gemm_ce<<<dim3(MT, NT), 128, DYNS>>>(targets, (float*)d_out);
}